// round 4
// baseline (speedup 1.0000x reference)
#include <cuda_runtime.h>
#include <cstdint>

#define NN 100000
#define NE 1600000
#define CH 64
#define OUTC 32
#define NB_SCAN ((NN + 1023) / 1024)   // 98

// ---------------- scratch (device globals; no allocation allowed) ----------------
__device__ int   g_deg[NN];
__device__ int   g_off[NN];
__device__ int   g_cur[NN];
__device__ float g_dinv[NN];
__device__ int   g_bsums[NB_SCAN];
__device__ int   g_boff[NB_SCAN];
__device__ __align__(16) int2  g_rw[NE];        // {src_row, bits(dinv[src_row])} sorted by target
__device__ __align__(16) float g_t[NN * CH];    // transformed features (GEMM out)
__device__ __align__(16) float g_h[NN * CH];    // aggregated + relu

typedef unsigned long long u64;

__device__ __forceinline__ u64 pack2(float lo, float hi) {
    u64 r; asm("mov.b64 %0, {%1, %2};" : "=l"(r) : "f"(lo), "f"(hi)); return r;
}
__device__ __forceinline__ void unpack2(u64 v, float& lo, float& hi) {
    asm("mov.b64 {%0, %1}, %2;" : "=f"(lo), "=f"(hi) : "l"(v));
}
__device__ __forceinline__ void fma2(u64& acc, u64 a, u64 b) {
    asm("fma.rn.f32x2 %0, %1, %2, %0;" : "+l"(acc) : "l"(a), "l"(b));
}

// ---------------- graph preprocessing ----------------
__global__ void k_zero_deg() {
    int i = blockIdx.x * 256 + threadIdx.x;
    if (i < NN) g_deg[i] = 0;
}

__global__ void k_count(const int* __restrict__ ei) {
    int e = blockIdx.x * 256 + threadIdx.x;
    if (e < NE) atomicAdd(&g_deg[ei[NE + e]], 1);
}

__global__ void k_scan1() {   // per-block (1024) exclusive scan of g_deg -> g_off, block sums -> g_bsums
    __shared__ int wsum[32];
    int tid = threadIdx.x;
    int i = blockIdx.x * 1024 + tid;
    int v = (i < NN) ? g_deg[i] : 0;
    int lane = tid & 31, wid = tid >> 5;
    int s = v;
#pragma unroll
    for (int d = 1; d < 32; d <<= 1) {
        int n = __shfl_up_sync(0xffffffffu, s, d);
        if (lane >= d) s += n;
    }
    if (lane == 31) wsum[wid] = s;
    __syncthreads();
    if (wid == 0) {
        int t = wsum[lane];
#pragma unroll
        for (int d = 1; d < 32; d <<= 1) {
            int n = __shfl_up_sync(0xffffffffu, t, d);
            if (lane >= d) t += n;
        }
        wsum[lane] = t;   // inclusive scan of warp totals
    }
    __syncthreads();
    int warpExcl = (wid > 0) ? wsum[wid - 1] : 0;
    if (i < NN) g_off[i] = warpExcl + (s - v);
    if (tid == 0) g_bsums[blockIdx.x] = wsum[31];
}

__global__ void k_scan2() {   // serial exclusive scan of 98 block sums
    if (threadIdx.x == 0) {
        int run = 0;
        for (int b = 0; b < NB_SCAN; b++) { int t = g_bsums[b]; g_boff[b] = run; run += t; }
    }
}

__global__ void k_scan3() {   // finalize offsets, init cursors, compute dinv (deg includes self-loop)
    int i = blockIdx.x * 256 + threadIdx.x;
    if (i < NN) {
        int o = g_off[i] + g_boff[i >> 10];
        g_off[i] = o;
        g_cur[i] = o;
        g_dinv[i] = rsqrtf((float)(g_deg[i] + 1));
    }
}

__global__ void k_fill(const int* __restrict__ ei) {
    int e = blockIdx.x * 256 + threadIdx.x;
    if (e < NE) {
        int r = ei[e];
        int c = ei[NE + e];
        int pos = atomicAdd(&g_cur[c], 1);
        g_rw[pos] = make_int2(r, __float_as_int(g_dinv[r]));
    }
}

// ---------------- GEMM: out[N, COUT] = X[N, 64] @ W[64, COUT] (+bias) ----------------
// 256 threads; each thread computes 2 rows x 8 cols using packed f32x2 FMA.
// SRC_H: read input from g_h instead of Xparam.  DST_PARAM: write to outparam instead of g_t.
template<int COUT, bool BIAS, bool SRC_H, bool DST_PARAM>
__global__ void k_gemm(const float* __restrict__ Xparam, const float* __restrict__ W,
                       const float* __restrict__ bias, float* __restrict__ outparam) {
    const float* X  = SRC_H ? (const float*)g_h : Xparam;
    float* out      = DST_PARAM ? outparam : (float*)g_t;

    constexpr int G   = COUT / 8;     // column groups per row
    constexpr int TR  = 256 / G;      // thread-rows
    constexpr int RPB = TR * 2;       // rows per block
    constexpr int XS  = 65;           // padded x stride (conflict-free broadcast reads)
    __shared__ __align__(16) float Wsh[CH * COUT];
    __shared__ float Xsh[RPB][XS];
    int tid = threadIdx.x;

    for (int i = tid; i < CH * COUT; i += 256) Wsh[i] = W[i];

    int row0 = blockIdx.x * RPB;
    {
        int k = tid & 63;
        for (int r = tid >> 6; r < RPB; r += 4) {
            int row = row0 + r;
            Xsh[r][k] = (row < NN) ? X[row * CH + k] : 0.f;
        }
    }
    __syncthreads();

    int cg = tid & (G - 1);
    int rt = tid / G;
    int r0 = rt * 2, r1 = r0 + 1;
    u64 acc0[4] = {0, 0, 0, 0};
    u64 acc1[4] = {0, 0, 0, 0};
    const float* wp = &Wsh[cg * 8];

#pragma unroll 4
    for (int k = 0; k < CH; k++) {
        float x0 = Xsh[r0][k];
        float x1 = Xsh[r1][k];
        u64 xp0 = pack2(x0, x0);
        u64 xp1 = pack2(x1, x1);
        ulonglong2 wa = *(const ulonglong2*)(wp + k * COUT);
        ulonglong2 wb = *(const ulonglong2*)(wp + k * COUT + 4);
        fma2(acc0[0], xp0, wa.x); fma2(acc0[1], xp0, wa.y);
        fma2(acc0[2], xp0, wb.x); fma2(acc0[3], xp0, wb.y);
        fma2(acc1[0], xp1, wa.x); fma2(acc1[1], xp1, wa.y);
        fma2(acc1[2], xp1, wb.x); fma2(acc1[3], xp1, wb.y);
    }

    float4 bb0 = make_float4(0, 0, 0, 0), bb1 = make_float4(0, 0, 0, 0);
    if (BIAS) {
        bb0 = *(const float4*)&bias[cg * 8];
        bb1 = *(const float4*)&bias[cg * 8 + 4];
    }
#pragma unroll
    for (int p = 0; p < 2; p++) {
        int row = row0 + (p == 0 ? r0 : r1);
        if (row < NN) {
            u64* acc = (p == 0) ? acc0 : acc1;
            float4 f0, f1;
            unpack2(acc[0], f0.x, f0.y); unpack2(acc[1], f0.z, f0.w);
            unpack2(acc[2], f1.x, f1.y); unpack2(acc[3], f1.z, f1.w);
            if (BIAS) {
                f0.x += bb0.x; f0.y += bb0.y; f0.z += bb0.z; f0.w += bb0.w;
                f1.x += bb1.x; f1.y += bb1.y; f1.z += bb1.z; f1.w += bb1.w;
            }
            *(float4*)&out[row * COUT + cg * 8]     = f0;
            *(float4*)&out[row * COUT + cg * 8 + 4] = f1;
        }
    }
}

// ---------------- Aggregation: one warp per node, 64 channels as float2/lane ----------------
// g_h[t] = relu( dinv[t] * sum_e dinv[r_e]*g_t[r_e]  +  dinv[t]^2 * g_t[t]  + bias )
__global__ void k_agg(const float* __restrict__ bias) {
    int gw   = (blockIdx.x * blockDim.x + threadIdx.x) >> 5;
    int lane = threadIdx.x & 31;
    if (gw >= NN) return;

    int start = g_off[gw];
    int cnt   = g_deg[gw];
    const float2* hp = (const float2*)g_t;

    float ax = 0.f, ay = 0.f;
    int e = start, end = start + cnt;
    for (; e + 4 <= end; e += 4) {
        int2 rw0 = g_rw[e];     int2 rw1 = g_rw[e + 1];
        int2 rw2 = g_rw[e + 2]; int2 rw3 = g_rw[e + 3];
        float2 v0 = hp[rw0.x * 32 + lane];
        float2 v1 = hp[rw1.x * 32 + lane];
        float2 v2 = hp[rw2.x * 32 + lane];
        float2 v3 = hp[rw3.x * 32 + lane];
        float w0 = __int_as_float(rw0.y), w1 = __int_as_float(rw1.y);
        float w2 = __int_as_float(rw2.y), w3 = __int_as_float(rw3.y);
        ax = fmaf(w0, v0.x, ax); ay = fmaf(w0, v0.y, ay);
        ax = fmaf(w1, v1.x, ax); ay = fmaf(w1, v1.y, ay);
        ax = fmaf(w2, v2.x, ax); ay = fmaf(w2, v2.y, ay);
        ax = fmaf(w3, v3.x, ax); ay = fmaf(w3, v3.y, ay);
    }
    for (; e < end; e++) {
        int2 rw = g_rw[e];
        float2 v = hp[rw.x * 32 + lane];
        float w = __int_as_float(rw.y);
        ax = fmaf(w, v.x, ax); ay = fmaf(w, v.y, ay);
    }

    float dt = g_dinv[gw];
    float2 sv = hp[gw * 32 + lane];
    float2 bb = ((const float2*)bias)[lane];
    float ox = fmaf(dt, ax, dt * dt * sv.x) + bb.x;
    float oy = fmaf(dt, ay, dt * dt * sv.y) + bb.y;
    ((float2*)g_h)[gw * 32 + lane] = make_float2(fmaxf(ox, 0.f), fmaxf(oy, 0.f));
}

// ---------------- launch ----------------
extern "C" void kernel_launch(void* const* d_in, const int* in_sizes, int n_in,
                              void* d_out, int out_size) {
    const float* x    = (const float*)d_in[0];
    const int*   ei   = (const int*)d_in[1];
    const float* W1   = (const float*)d_in[2];
    const float* b1   = (const float*)d_in[3];
    const float* W2   = (const float*)d_in[4];
    const float* b2   = (const float*)d_in[5];
    const float* Wlin = (const float*)d_in[6];
    const float* blin = (const float*)d_in[7];
    float* out = (float*)d_out;

    // CSR build (once per launch; shared by both GCN layers)
    k_zero_deg<<<(NN + 255) / 256, 256>>>();
    k_count<<<(NE + 255) / 256, 256>>>(ei);
    k_scan1<<<NB_SCAN, 1024>>>();
    k_scan2<<<1, 32>>>();
    k_scan3<<<(NN + 255) / 256, 256>>>();
    k_fill<<<(NE + 255) / 256, 256>>>(ei);

    // layer 1: x -> g_t -> g_h
    k_gemm<64, false, false, false><<<(NN + 63) / 64, 256>>>(x, W1, nullptr, nullptr);
    k_agg<<<(NN + 7) / 8, 256>>>(b1);
    // layer 2: g_h -> g_t -> g_h
    k_gemm<64, false, true, false><<<(NN + 63) / 64, 256>>>(nullptr, W2, nullptr, nullptr);
    k_agg<<<(NN + 7) / 8, 256>>>(b2);
    // linear head: g_h -> out
    k_gemm<32, true, true, true><<<(NN + 127) / 128, 256>>>(nullptr, Wlin, blin, out);
}